// round 11
// baseline (speedup 1.0000x reference)
#include <cuda_runtime.h>
#include <cuda_bf16.h>
#include <math.h>
#include <stdint.h>

#define T_TOK  8192
#define D_IN   1024
#define D_HID  4096
#define NE     8
#define TOPK   2

#define BM 128
#define BN 256
#define BK 32
#define PADM   (T_TOK*TOPK + NE*BM)   /* 17408 */
#define MTILES (PADM/BM)              /* 136 */

#define APAD 40    /* halfs per A smem row (32 data + 8 pad) */
#define BPAD 264   /* halfs per B smem row (256 data + 8 pad) */
#define AH_OFF 0
#define AL_OFF (BM*APAD)                 /* 5120 halfs */
#define BH_OFF (2*BM*APAD)               /* 10240 */
#define BL_OFF (2*BM*APAD + BK*BPAD)     /* 18688 */
#define ST_H   (2*BM*APAD + 2*BK*BPAD)   /* 27136 halfs per stage */
#define NSTG   3
#define SMEM_BYTES (NSTG*ST_H*2)         /* 162816 B */

typedef __nv_bfloat16  bf16;
typedef __nv_bfloat162 bf162;

// ---------------- scratch (static device globals; no allocation) ----------
__device__ __align__(16) bf16 g_xh [(size_t)T_TOK*D_IN];
__device__ __align__(16) bf16 g_xl [(size_t)T_TOK*D_IN];
__device__ __align__(16) bf16 g_w1h[(size_t)NE*D_IN*D_HID];
__device__ __align__(16) bf16 g_w1l[(size_t)NE*D_IN*D_HID];
__device__ __align__(16) bf16 g_w2h[(size_t)NE*D_HID*D_IN];
__device__ __align__(16) bf16 g_w2l[(size_t)NE*D_HID*D_IN];
__device__ __align__(16) bf16 g_hh [(size_t)PADM*D_HID];
__device__ __align__(16) bf16 g_hl [(size_t)PADM*D_HID];
__device__ int   g_sel[T_TOK*TOPK];
__device__ float g_wt [T_TOK*TOPK];
__device__ float g_wtp[PADM];
__device__ float g_prob_sum[NE];
__device__ int   g_count[NE];
__device__ int   g_fill[NE];
__device__ int   g_poff[NE+1];
__device__ int   g_ptot;
__device__ int   g_ptok[PADM];

// ---------------- split helper ---------------------------------------------
__device__ __forceinline__ void split4(float4 v, bf162* h, bf162* l, int idx2) {
    bf16 h0 = __float2bfloat16(v.x), h1 = __float2bfloat16(v.y);
    bf16 h2 = __float2bfloat16(v.z), h3 = __float2bfloat16(v.w);
    bf16 l0 = __float2bfloat16(v.x - __bfloat162float(h0));
    bf16 l1 = __float2bfloat16(v.y - __bfloat162float(h1));
    bf16 l2 = __float2bfloat16(v.z - __bfloat162float(h2));
    bf16 l3 = __float2bfloat16(v.w - __bfloat162float(h3));
    bf162 a; a.x = h0; a.y = h1;
    bf162 b; b.x = h2; b.y = h3;
    h[idx2] = a; h[idx2 + 1] = b;
    a.x = l0; a.y = l1; b.x = l2; b.y = l3;
    l[idx2] = a; l[idx2 + 1] = b;
}

// ---------------- launch 0: split x/W1/W2 + init counters/ptok -------------
#define NX4  (T_TOK*D_IN/4)          /* 2097152 */
#define NW4  (NE*D_IN*D_HID/4)       /* 8388608 */
#define NTOT4 (NX4 + 2*NW4)          /* 18874368 */

__global__ void split_all(const float4* __restrict__ x, const float4* __restrict__ W1,
                          const float4* __restrict__ W2) {
    int i = blockIdx.x * blockDim.x + threadIdx.x;
    // fused init (runs before router/route/gemm launches)
    if (i < PADM) g_ptok[i] = -1;
    if (i < NE) { g_prob_sum[i] = 0.f; g_count[i] = 0; g_fill[i] = 0; }

    if (i < NX4) {
        split4(x[i], (bf162*)g_xh, (bf162*)g_xl, 2 * i);
    } else if (i < NX4 + NW4) {
        int j = i - NX4;
        split4(W1[j], (bf162*)g_w1h, (bf162*)g_w1l, 2 * j);
    } else if (i < NTOT4) {
        int j = i - NX4 - NW4;
        split4(W2[j], (bf162*)g_w2h, (bf162*)g_w2l, 2 * j);
    }
}

// ---------------- launch 1: router (blocks 0..1023) + zero out (all) -------
__global__ void prep_k(const float* __restrict__ x, const float* __restrict__ gw,
                       float4* __restrict__ out4) {
    // every block zeroes its 256-float4 slice of the output
    {
        int i = blockIdx.x * blockDim.x + threadIdx.x;
        if (i < T_TOK * D_IN / 4) out4[i] = make_float4(0.f, 0.f, 0.f, 0.f);
    }
    if (blockIdx.x >= T_TOK / 8) return;

    __shared__ float sg[D_IN * NE];
    __shared__ float s_prob[NE];
    __shared__ int   s_cnt[NE];
    int tid = threadIdx.x;
    for (int i = tid; i < D_IN * NE; i += 256) sg[i] = gw[i];
    if (tid < NE) { s_prob[tid] = 0.f; s_cnt[tid] = 0; }
    __syncthreads();

    int warp = tid >> 5, lane = tid & 31;
    int t = blockIdx.x * 8 + warp;
    const float* xr = x + (size_t)t * D_IN;

    float acc[NE];
#pragma unroll
    for (int e = 0; e < NE; e++) acc[e] = 0.f;
    for (int i = lane; i < D_IN; i += 32) {
        float xv = xr[i];
        const float* g = &sg[i * NE];
#pragma unroll
        for (int e = 0; e < NE; e++) acc[e] += xv * g[e];
    }
#pragma unroll
    for (int e = 0; e < NE; e++)
        for (int o = 16; o; o >>= 1) acc[e] += __shfl_xor_sync(0xffffffffu, acc[e], o);

    if (lane == 0) {
        float mx = acc[0];
#pragma unroll
        for (int e = 1; e < NE; e++) mx = fmaxf(mx, acc[e]);
        float p[NE], s = 0.f;
#pragma unroll
        for (int e = 0; e < NE; e++) { p[e] = expf(acc[e] - mx); s += p[e]; }
        float inv = 1.f / s;
#pragma unroll
        for (int e = 0; e < NE; e++) p[e] *= inv;

        int i1 = 0;
#pragma unroll
        for (int e = 1; e < NE; e++) if (p[e] > p[i1]) i1 = e;
        int i2 = (i1 == 0) ? 1 : 0;
#pragma unroll
        for (int e = 0; e < NE; e++) if (e != i1 && p[e] > p[i2]) i2 = e;

        float d = p[i1] + p[i2] + 1e-6f;
        g_sel[t*2]   = i1;  g_sel[t*2+1] = i2;
        g_wt [t*2]   = p[i1] / d;
        g_wt [t*2+1] = p[i2] / d;
#pragma unroll
        for (int e = 0; e < NE; e++) atomicAdd(&s_prob[e], p[e]);
        atomicAdd(&s_cnt[i1], 1);
        atomicAdd(&s_cnt[i2], 1);
    }
    __syncthreads();
    if (tid < NE) {
        atomicAdd(&g_prob_sum[tid], s_prob[tid]);
        atomicAdd(&g_count[tid], s_cnt[tid]);
    }
}

// ---------------- launch 2: offsets + scatter (single block) ---------------
__global__ void route_k() {
    int tid = threadIdx.x;
    if (tid == 0) {
        int off = 0;
        for (int e = 0; e < NE; e++) {
            g_poff[e] = off;
            off += ((g_count[e] + BM - 1) / BM) * BM;
        }
        g_poff[NE] = off;
        g_ptot = off;
    }
    __syncthreads();
    for (int t = tid; t < T_TOK; t += 256) {
#pragma unroll
        for (int k = 0; k < TOPK; k++) {
            int e = g_sel[t*2 + k];
            int j = atomicAdd(&g_fill[e], 1);
            int pos = g_poff[e] + j;
            g_ptok[pos] = t;
            g_wtp[pos]  = g_wt[t*2 + k];
        }
    }
}

// ---------------- MMA helpers ----------------------------------------------
__device__ __forceinline__ void cpa16(uint32_t dst, const void* src) {
    asm volatile("cp.async.cg.shared.global [%0], [%1], 16;\n" :: "r"(dst), "l"(src));
}
__device__ __forceinline__ void ldmx4(uint32_t* r, uint32_t addr) {
    asm volatile("ldmatrix.sync.aligned.m8n8.x4.shared.b16 {%0,%1,%2,%3}, [%4];\n"
        : "=r"(r[0]), "=r"(r[1]), "=r"(r[2]), "=r"(r[3]) : "r"(addr));
}
__device__ __forceinline__ void ldmx4t(uint32_t* r, uint32_t addr) {
    asm volatile("ldmatrix.sync.aligned.m8n8.x4.trans.shared.b16 {%0,%1,%2,%3}, [%4];\n"
        : "=r"(r[0]), "=r"(r[1]), "=r"(r[2]), "=r"(r[3]) : "r"(addr));
}
__device__ __forceinline__ void mma16816(float* c, const uint32_t* a, const uint32_t* b) {
    asm volatile("mma.sync.aligned.m16n8k16.row.col.f32.bf16.bf16.f32 "
        "{%0,%1,%2,%3}, {%4,%5,%6,%7}, {%8,%9}, {%0,%1,%2,%3};\n"
        : "+f"(c[0]), "+f"(c[1]), "+f"(c[2]), "+f"(c[3])
        : "r"(a[0]), "r"(a[1]), "r"(a[2]), "r"(a[3]), "r"(b[0]), "r"(b[1]));
}
__device__ __forceinline__ float gelu_exact(float v) {
    return 0.5f * v * (1.0f + erff(v * 0.70710678118654752440f));
}

// ---------------- split-precision MMA GEMM (128x256 tile) ------------------
// FIRST=true : A gathered by token, epilogue = bias+GELU -> hi/lo bf16 hidden
// FIRST=false: A = permuted hidden rows, epilogue = (acc+bias)*w atomicAdd out
template<int KD, int ND, bool FIRST>
__global__ void __launch_bounds__(256, 1) gemm_mma(
    const bf16* __restrict__ Ah_g, const bf16* __restrict__ Al_g,
    const bf16* __restrict__ Bh_g, const bf16* __restrict__ Bl_g,
    const float* __restrict__ bias, float* __restrict__ out)
{
    extern __shared__ bf16 smem[];
    __shared__ int   s_tok[BM];
    __shared__ float s_w[BM];

    int row0 = blockIdx.y * BM;
    if (row0 >= g_ptot) return;
    int e = 0;
    while (row0 >= g_poff[e + 1]) e++;
    int n0 = blockIdx.x * BN;

    int tid = threadIdx.x;
    if (tid < BM) {
        int t = g_ptok[row0 + tid];
        s_tok[tid] = t;
        if (!FIRST) s_w[tid] = g_wtp[row0 + tid];
    }
    __syncthreads();

    const bf16* Bh_e = Bh_g + (size_t)e * KD * ND + n0;
    const bf16* Bl_e = Bl_g + (size_t)e * KD * ND + n0;

    uint32_t smem_base = (uint32_t)__cvta_generic_to_shared(smem);

    auto load_stage = [&](int stage, int k0) {
        uint32_t sb = smem_base + (uint32_t)stage * (ST_H * 2);
        // A: 128 rows x 4 chunks(16B) x {h,l} = 1024 cp.async
#pragma unroll
        for (int m = 0; m < 4; m++) {
            int c = tid + m * 256;
            int hl = c & 1, j = (c >> 1) & 3, r = c >> 3;
            int tk = s_tok[r];
            size_t arow = FIRST ? (size_t)(tk < 0 ? 0 : tk) * KD : (size_t)(row0 + r) * KD;
            uint32_t offA = (uint32_t)(r * APAD + j * 8) * 2;
            cpa16(sb + (hl ? AL_OFF : AH_OFF) * 2 + offA,
                  (hl ? Al_g : Ah_g) + arow + k0 + j * 8);
        }
        // B: 32 rows x 32 chunks(16B) x {h,l} = 2048 cp.async
#pragma unroll
        for (int m = 0; m < 8; m++) {
            int c = tid + m * 256;
            int hl = c & 1, jb = (c >> 1) & 31, rb = c >> 6;
            size_t brow = (size_t)(k0 + rb) * ND + jb * 8;
            uint32_t offB = (uint32_t)(rb * BPAD + jb * 8) * 2;
            cpa16(sb + (hl ? BL_OFF : BH_OFF) * 2 + offB, (hl ? Bl_e : Bh_e) + brow);
        }
    };

    int lane = tid & 31, warp = tid >> 5;
    int wm = (warp >> 2) * 64;   // 2 warp-rows x 64
    int wn = (warp & 3) * 64;    // 4 warp-cols x 64
    uint32_t rowSel = (lane & 7) + ((lane >> 3) & 1) * 8;
    uint32_t colSel = (lane >> 4) * 8;

    float acc[4][8][4];
#pragma unroll
    for (int i = 0; i < 4; i++)
#pragma unroll
        for (int j = 0; j < 8; j++)
#pragma unroll
            for (int q = 0; q < 4; q++) acc[i][j][q] = 0.f;

    auto compute = [&](int stage) {
        uint32_t sb = smem_base + (uint32_t)stage * (ST_H * 2);
        uint32_t ah = sb + AH_OFF * 2, al = sb + AL_OFF * 2;
        uint32_t bh = sb + BH_OFF * 2, bl = sb + BL_OFF * 2;
#pragma unroll
        for (int kk = 0; kk < 2; kk++) {
            int k16 = kk * 16;
            uint32_t bhF[4][4], blF[4][4];
#pragma unroll
            for (int nj = 0; nj < 4; nj++) {
                uint32_t off = (uint32_t)((k16 + rowSel) * BPAD + wn + nj * 16 + colSel) * 2;
                ldmx4t(bhF[nj], bh + off);
                ldmx4t(blF[nj], bl + off);
            }
            uint32_t aF[4][4];
#pragma unroll
            for (int mi = 0; mi < 4; mi++) {
                uint32_t off = (uint32_t)((wm + mi * 16 + rowSel) * APAD + k16 + colSel) * 2;
                ldmx4(aF[mi], ah + off);
            }
#pragma unroll
            for (int mi = 0; mi < 4; mi++)
#pragma unroll
                for (int ni = 0; ni < 8; ni++) {
                    mma16816(acc[mi][ni], aF[mi], &bhF[ni >> 1][(ni & 1) * 2]);
                    mma16816(acc[mi][ni], aF[mi], &blF[ni >> 1][(ni & 1) * 2]);
                }
#pragma unroll
            for (int mi = 0; mi < 4; mi++) {
                uint32_t off = (uint32_t)((wm + mi * 16 + rowSel) * APAD + k16 + colSel) * 2;
                ldmx4(aF[mi], al + off);
            }
#pragma unroll
            for (int mi = 0; mi < 4; mi++)
#pragma unroll
                for (int ni = 0; ni < 8; ni++)
                    mma16816(acc[mi][ni], aF[mi], &bhF[ni >> 1][(ni & 1) * 2]);
        }
    };

    const int NIT = KD / BK;
    load_stage(0, 0);
    asm volatile("cp.async.commit_group;\n");
    load_stage(1, BK);
    asm volatile("cp.async.commit_group;\n");

#pragma unroll 1
    for (int it = 0; it < NIT; ++it) {
        asm volatile("cp.async.wait_group 1;\n");
        __syncthreads();
        int s = it % NSTG;
        compute(s);
        if (it + 2 < NIT) {
            int s2 = (it + 2) % NSTG;
            load_stage(s2, (it + 2) * BK);
        }
        asm volatile("cp.async.commit_group;\n");   // always: uniform group count
    }

    int g = lane >> 2, tg = lane & 3;
#pragma unroll
    for (int mi = 0; mi < 4; mi++)
#pragma unroll
        for (int ni = 0; ni < 8; ni++)
#pragma unroll
            for (int h = 0; h < 2; h++) {
                int m = wm + mi * 16 + g + h * 8;
                int n = n0 + wn + ni * 8 + 2 * tg;
                float v0 = acc[mi][ni][h * 2 + 0] + bias[e * ND + n];
                float v1 = acc[mi][ni][h * 2 + 1] + bias[e * ND + n + 1];
                if (FIRST) {
                    if (s_tok[m] < 0) continue;
                    size_t orow = (size_t)(row0 + m) * ND + n;
                    v0 = gelu_exact(v0);
                    v1 = gelu_exact(v1);
                    bf16 h0 = __float2bfloat16(v0), h1 = __float2bfloat16(v1);
                    bf16 l0 = __float2bfloat16(v0 - __bfloat162float(h0));
                    bf16 l1 = __float2bfloat16(v1 - __bfloat162float(h1));
                    bf162 ph; ph.x = h0; ph.y = h1;
                    bf162 pl; pl.x = l0; pl.y = l1;
                    *(bf162*)&g_hh[orow] = ph;
                    *(bf162*)&g_hl[orow] = pl;
                } else {
                    int tok = s_tok[m];
                    if (tok < 0) continue;
                    float w = s_w[m];
                    atomicAdd(&out[(size_t)tok * ND + n],     v0 * w);
                    atomicAdd(&out[(size_t)tok * ND + n + 1], v1 * w);
                }
            }
}

// ---------------- aux loss -------------------------------------------------
__global__ void aux_k(float* __restrict__ out, int out_size) {
    if (out_size <= T_TOK * D_IN) return;
    float s = 0.f;
    for (int e = 0; e < NE; e++) {
        float mean_prob = g_prob_sum[e] / (float)T_TOK;
        float frac = (float)g_count[e] / (float)(T_TOK * TOPK);
        s += mean_prob * frac;
    }
    out[T_TOK * D_IN] = (float)NE * s;
}

// ---------------- launch ---------------------------------------------------
extern "C" void kernel_launch(void* const* d_in, const int* in_sizes, int n_in,
                              void* d_out, int out_size) {
    const float* x   = (const float*)d_in[0];
    const float* gw  = (const float*)d_in[1];
    const float* W1  = (const float*)d_in[2];
    const float* b1  = (const float*)d_in[3];
    const float* W2  = (const float*)d_in[4];
    const float* b2  = (const float*)d_in[5];
    float* out = (float*)d_out;

    cudaFuncSetAttribute(gemm_mma<D_IN, D_HID, true>,
                         cudaFuncAttributeMaxDynamicSharedMemorySize, SMEM_BYTES);
    cudaFuncSetAttribute(gemm_mma<D_HID, D_IN, false>,
                         cudaFuncAttributeMaxDynamicSharedMemorySize, SMEM_BYTES);

    bf16 *xh, *xl, *w1h, *w1l, *w2h, *w2l, *hh, *hl;
    cudaGetSymbolAddress((void**)&xh,  g_xh);
    cudaGetSymbolAddress((void**)&xl,  g_xl);
    cudaGetSymbolAddress((void**)&w1h, g_w1h);
    cudaGetSymbolAddress((void**)&w1l, g_w1l);
    cudaGetSymbolAddress((void**)&w2h, g_w2h);
    cudaGetSymbolAddress((void**)&w2l, g_w2l);
    cudaGetSymbolAddress((void**)&hh,  g_hh);
    cudaGetSymbolAddress((void**)&hl,  g_hl);

    // launch 0: fused split of x/W1/W2 + init of counters/ptok
    split_all<<<NTOT4 / 256, 256>>>((const float4*)x, (const float4*)W1, (const float4*)W2);
    // launch 1: router + zero output
    prep_k<<<T_TOK * D_IN / 4 / 256, 256>>>(x, gw, (float4*)out);
    // launch 2: offsets + scatter (single block)
    route_k<<<1, 256>>>();

    // launch 3 (profiled slot): GEMM1
    gemm_mma<D_IN, D_HID, true>
        <<<dim3(D_HID / BN, MTILES), 256, SMEM_BYTES>>>(xh, xl, w1h, w1l, b1, out);
    // launch 4: GEMM2 + fused combine
    gemm_mma<D_HID, D_IN, false>
        <<<dim3(D_IN / BN, MTILES), 256, SMEM_BYTES>>>(hh, hl, w2h, w2l, b2, out);

    // launch 5: aux loss
    aux_k<<<1, 1>>>(out, out_size);
}

// round 15
// speedup vs baseline: 1.1039x; 1.1039x over previous
#include <cuda_runtime.h>
#include <cuda_bf16.h>
#include <math.h>
#include <stdint.h>

#define T_TOK  8192
#define D_IN   1024
#define D_HID  4096
#define NE     8
#define TOPK   2

#define BM 128
#define BN 128
#define BK 32
#define PADM   (T_TOK*TOPK + NE*BM)   /* 17408 */
#define MTILES (PADM/BM)              /* 136 */

#define APAD 40    /* halfs per A smem row (32 data + 8 pad) */
#define BPAD 136   /* halfs per B smem row (128 data + 8 pad) */
#define AH_OFF 0
#define AL_OFF (BM*APAD)
#define BH_OFF (2*BM*APAD)
#define BL_OFF (2*BM*APAD + BK*BPAD)
#define ST_H   (2*BM*APAD + 2*BK*BPAD)   /* 18944 halfs per stage */
#define NSTG   3
#define SMEM_BYTES (NSTG*ST_H*2)         /* 113664 B -> 2 CTAs/SM */

typedef __nv_bfloat16  bf16;
typedef __nv_bfloat162 bf162;

// ---------------- scratch (static device globals; no allocation) ----------
__device__ __align__(16) bf16 g_xh [(size_t)T_TOK*D_IN];
__device__ __align__(16) bf16 g_xl [(size_t)T_TOK*D_IN];
__device__ __align__(16) bf16 g_w1h[(size_t)NE*D_IN*D_HID];
__device__ __align__(16) bf16 g_w1l[(size_t)NE*D_IN*D_HID];
__device__ __align__(16) bf16 g_w2h[(size_t)NE*D_HID*D_IN];
__device__ __align__(16) bf16 g_w2l[(size_t)NE*D_HID*D_IN];
__device__ __align__(16) bf16 g_hh [(size_t)PADM*D_HID];
__device__ __align__(16) bf16 g_hl [(size_t)PADM*D_HID];
__device__ int   g_sel[T_TOK*TOPK];
__device__ float g_wt [T_TOK*TOPK];
__device__ float g_wtp[PADM];
__device__ float g_prob_sum[NE];
__device__ int   g_count[NE];
__device__ int   g_fill[NE];
__device__ int   g_poff[NE+1];
__device__ int   g_ptot;
__device__ int   g_ptok[PADM];

// ---------------- split helper ---------------------------------------------
__device__ __forceinline__ void split4(float4 v, bf162* h, bf162* l, int idx2) {
    bf16 h0 = __float2bfloat16(v.x), h1 = __float2bfloat16(v.y);
    bf16 h2 = __float2bfloat16(v.z), h3 = __float2bfloat16(v.w);
    bf16 l0 = __float2bfloat16(v.x - __bfloat162float(h0));
    bf16 l1 = __float2bfloat16(v.y - __bfloat162float(h1));
    bf16 l2 = __float2bfloat16(v.z - __bfloat162float(h2));
    bf16 l3 = __float2bfloat16(v.w - __bfloat162float(h3));
    bf162 a; a.x = h0; a.y = h1;
    bf162 b; b.x = h2; b.y = h3;
    h[idx2] = a; h[idx2 + 1] = b;
    a.x = l0; a.y = l1; b.x = l2; b.y = l3;
    l[idx2] = a; l[idx2 + 1] = b;
}

// ---------------- launch 0: split x/W1/W2 + init counters/ptok -------------
#define NX4  (T_TOK*D_IN/4)
#define NW4  (NE*D_IN*D_HID/4)
#define NTOT4 (NX4 + 2*NW4)

__global__ void split_all(const float4* __restrict__ x, const float4* __restrict__ W1,
                          const float4* __restrict__ W2) {
    int i = blockIdx.x * blockDim.x + threadIdx.x;
    if (i < PADM) g_ptok[i] = -1;
    if (i < NE) { g_prob_sum[i] = 0.f; g_count[i] = 0; g_fill[i] = 0; }

    if (i < NX4) {
        split4(x[i], (bf162*)g_xh, (bf162*)g_xl, 2 * i);
    } else if (i < NX4 + NW4) {
        int j = i - NX4;
        split4(W1[j], (bf162*)g_w1h, (bf162*)g_w1l, 2 * j);
    } else if (i < NTOT4) {
        int j = i - NX4 - NW4;
        split4(W2[j], (bf162*)g_w2h, (bf162*)g_w2l, 2 * j);
    }
}

// ---------------- launch 1: router (blocks 0..1023) + zero out (all) -------
__global__ void prep_k(const float* __restrict__ x, const float* __restrict__ gw,
                       float4* __restrict__ out4) {
    {
        int i = blockIdx.x * blockDim.x + threadIdx.x;
        if (i < T_TOK * D_IN / 4) out4[i] = make_float4(0.f, 0.f, 0.f, 0.f);
    }
    if (blockIdx.x >= T_TOK / 8) return;

    __shared__ float sg[D_IN * NE];
    __shared__ float s_prob[NE];
    __shared__ int   s_cnt[NE];
    int tid = threadIdx.x;
    for (int i = tid; i < D_IN * NE; i += 256) sg[i] = gw[i];
    if (tid < NE) { s_prob[tid] = 0.f; s_cnt[tid] = 0; }
    __syncthreads();

    int warp = tid >> 5, lane = tid & 31;
    int t = blockIdx.x * 8 + warp;
    const float* xr = x + (size_t)t * D_IN;

    float acc[NE];
#pragma unroll
    for (int e = 0; e < NE; e++) acc[e] = 0.f;
    for (int i = lane; i < D_IN; i += 32) {
        float xv = xr[i];
        const float* g = &sg[i * NE];
#pragma unroll
        for (int e = 0; e < NE; e++) acc[e] += xv * g[e];
    }
#pragma unroll
    for (int e = 0; e < NE; e++)
        for (int o = 16; o; o >>= 1) acc[e] += __shfl_xor_sync(0xffffffffu, acc[e], o);

    if (lane == 0) {
        float mx = acc[0];
#pragma unroll
        for (int e = 1; e < NE; e++) mx = fmaxf(mx, acc[e]);
        float p[NE], s = 0.f;
#pragma unroll
        for (int e = 0; e < NE; e++) { p[e] = expf(acc[e] - mx); s += p[e]; }
        float inv = 1.f / s;
#pragma unroll
        for (int e = 0; e < NE; e++) p[e] *= inv;

        int i1 = 0;
#pragma unroll
        for (int e = 1; e < NE; e++) if (p[e] > p[i1]) i1 = e;
        int i2 = (i1 == 0) ? 1 : 0;
#pragma unroll
        for (int e = 0; e < NE; e++) if (e != i1 && p[e] > p[i2]) i2 = e;

        float d = p[i1] + p[i2] + 1e-6f;
        g_sel[t*2]   = i1;  g_sel[t*2+1] = i2;
        g_wt [t*2]   = p[i1] / d;
        g_wt [t*2+1] = p[i2] / d;
#pragma unroll
        for (int e = 0; e < NE; e++) atomicAdd(&s_prob[e], p[e]);
        atomicAdd(&s_cnt[i1], 1);
        atomicAdd(&s_cnt[i2], 1);
    }
    __syncthreads();
    if (tid < NE) {
        atomicAdd(&g_prob_sum[tid], s_prob[tid]);
        atomicAdd(&g_count[tid], s_cnt[tid]);
    }
}

// ---------------- launch 2: offsets + scatter (single block) ---------------
__global__ void route_k() {
    int tid = threadIdx.x;
    if (tid == 0) {
        int off = 0;
        for (int e = 0; e < NE; e++) {
            g_poff[e] = off;
            off += ((g_count[e] + BM - 1) / BM) * BM;
        }
        g_poff[NE] = off;
        g_ptot = off;
    }
    __syncthreads();
    for (int t = tid; t < T_TOK; t += 256) {
#pragma unroll
        for (int k = 0; k < TOPK; k++) {
            int e = g_sel[t*2 + k];
            int j = atomicAdd(&g_fill[e], 1);
            int pos = g_poff[e] + j;
            g_ptok[pos] = t;
            g_wtp[pos]  = g_wt[t*2 + k];
        }
    }
}

// ---------------- MMA helpers ----------------------------------------------
__device__ __forceinline__ void cpa16(uint32_t dst, const void* src) {
    asm volatile("cp.async.cg.shared.global [%0], [%1], 16;\n" :: "r"(dst), "l"(src));
}
__device__ __forceinline__ void ldmx4(uint32_t* r, uint32_t addr) {
    asm volatile("ldmatrix.sync.aligned.m8n8.x4.shared.b16 {%0,%1,%2,%3}, [%4];\n"
        : "=r"(r[0]), "=r"(r[1]), "=r"(r[2]), "=r"(r[3]) : "r"(addr));
}
__device__ __forceinline__ void ldmx4t(uint32_t* r, uint32_t addr) {
    asm volatile("ldmatrix.sync.aligned.m8n8.x4.trans.shared.b16 {%0,%1,%2,%3}, [%4];\n"
        : "=r"(r[0]), "=r"(r[1]), "=r"(r[2]), "=r"(r[3]) : "r"(addr));
}
__device__ __forceinline__ void mma16816(float* c, const uint32_t* a, const uint32_t* b) {
    asm volatile("mma.sync.aligned.m16n8k16.row.col.f32.bf16.bf16.f32 "
        "{%0,%1,%2,%3}, {%4,%5,%6,%7}, {%8,%9}, {%0,%1,%2,%3};\n"
        : "+f"(c[0]), "+f"(c[1]), "+f"(c[2]), "+f"(c[3])
        : "r"(a[0]), "r"(a[1]), "r"(a[2]), "r"(a[3]), "r"(b[0]), "r"(b[1]));
}
__device__ __forceinline__ float gelu_exact(float v) {
    return 0.5f * v * (1.0f + erff(v * 0.70710678118654752440f));
}

// ---------------- split-precision MMA GEMM (128x128 tile, 2 CTAs/SM) -------
// FIRST=true : A gathered by token, epilogue = bias+GELU -> hi/lo bf16 hidden
// FIRST=false: A = permuted hidden rows, epilogue = (acc+bias)*w atomicAdd out
template<int KD, int ND, bool FIRST>
__global__ void __launch_bounds__(256, 2) gemm_mma(
    const bf16* __restrict__ Ah_g, const bf16* __restrict__ Al_g,
    const bf16* __restrict__ Bh_g, const bf16* __restrict__ Bl_g,
    const float* __restrict__ bias, float* __restrict__ out)
{
    extern __shared__ bf16 smem[];
    __shared__ int   s_tok[BM];
    __shared__ float s_w[BM];

    int row0 = blockIdx.y * BM;
    if (row0 >= g_ptot) return;
    int e = 0;
    while (row0 >= g_poff[e + 1]) e++;
    int n0 = blockIdx.x * BN;

    int tid = threadIdx.x;
    if (tid < BM) {
        int t = g_ptok[row0 + tid];
        s_tok[tid] = t;
        if (!FIRST) s_w[tid] = g_wtp[row0 + tid];
    }
    __syncthreads();

    const bf16* Bh_e = Bh_g + (size_t)e * KD * ND + n0;
    const bf16* Bl_e = Bl_g + (size_t)e * KD * ND + n0;

    uint32_t smem_base = (uint32_t)__cvta_generic_to_shared(smem);

    auto load_stage = [&](int stage, int k0) {
        uint32_t sb = smem_base + (uint32_t)stage * (ST_H * 2);
#pragma unroll
        for (int m = 0; m < 2; m++) {
            int c = tid + m * 256;              // 0..511
            int r = c >> 2, j = c & 3;          // A: 128 rows x 4 chunks(16B)
            int tk = s_tok[r];
            size_t arow = FIRST ? (size_t)(tk < 0 ? 0 : tk) * KD : (size_t)(row0 + r) * KD;
            uint32_t offA = (uint32_t)(r * APAD + j * 8) * 2;
            cpa16(sb + AH_OFF * 2 + offA, Ah_g + arow + k0 + j * 8);
            cpa16(sb + AL_OFF * 2 + offA, Al_g + arow + k0 + j * 8);
            int rb = c >> 4, jb = c & 15;       // B: 32 rows x 16 chunks(16B)
            size_t brow = (size_t)(k0 + rb) * ND + jb * 8;
            uint32_t offB = (uint32_t)(rb * BPAD + jb * 8) * 2;
            cpa16(sb + BH_OFF * 2 + offB, Bh_e + brow);
            cpa16(sb + BL_OFF * 2 + offB, Bl_e + brow);
        }
    };

    int lane = tid & 31, warp = tid >> 5;
    int wm = (warp >> 2) * 64;
    int wn = (warp & 3) * 32;
    uint32_t rowSel = (lane & 7) + ((lane >> 3) & 1) * 8;
    uint32_t colSel = (lane >> 4) * 8;

    float acc[4][4][4];
#pragma unroll
    for (int i = 0; i < 4; i++)
#pragma unroll
        for (int j = 0; j < 4; j++)
#pragma unroll
            for (int q = 0; q < 4; q++) acc[i][j][q] = 0.f;

    auto compute = [&](int stage) {
        uint32_t sb = smem_base + (uint32_t)stage * (ST_H * 2);
        uint32_t ah = sb + AH_OFF * 2, al = sb + AL_OFF * 2;
        uint32_t bh = sb + BH_OFF * 2, bl = sb + BL_OFF * 2;
#pragma unroll
        for (int kk = 0; kk < 2; kk++) {
            int k16 = kk * 16;
            uint32_t bhF[2][4], blF[2][4];
#pragma unroll
            for (int nj = 0; nj < 2; nj++) {
                uint32_t off = (uint32_t)((k16 + rowSel) * BPAD + wn + nj * 16 + colSel) * 2;
                ldmx4t(bhF[nj], bh + off);
                ldmx4t(blF[nj], bl + off);
            }
            uint32_t aF[4][4];
#pragma unroll
            for (int mi = 0; mi < 4; mi++) {
                uint32_t off = (uint32_t)((wm + mi * 16 + rowSel) * APAD + k16 + colSel) * 2;
                ldmx4(aF[mi], ah + off);
            }
#pragma unroll
            for (int mi = 0; mi < 4; mi++)
#pragma unroll
                for (int ni = 0; ni < 4; ni++) {
                    mma16816(acc[mi][ni], aF[mi], &bhF[ni >> 1][(ni & 1) * 2]);
                    mma16816(acc[mi][ni], aF[mi], &blF[ni >> 1][(ni & 1) * 2]);
                }
#pragma unroll
            for (int mi = 0; mi < 4; mi++) {
                uint32_t off = (uint32_t)((wm + mi * 16 + rowSel) * APAD + k16 + colSel) * 2;
                ldmx4(aF[mi], al + off);
            }
#pragma unroll
            for (int mi = 0; mi < 4; mi++)
#pragma unroll
                for (int ni = 0; ni < 4; ni++)
                    mma16816(acc[mi][ni], aF[mi], &bhF[ni >> 1][(ni & 1) * 2]);
        }
    };

    const int NIT = KD / BK;
    load_stage(0, 0);
    asm volatile("cp.async.commit_group;\n");
    load_stage(1, BK);
    asm volatile("cp.async.commit_group;\n");

#pragma unroll 1
    for (int it = 0; it < NIT; ++it) {
        asm volatile("cp.async.wait_group 1;\n");
        __syncthreads();
        int s = it % NSTG;
        compute(s);
        if (it + 2 < NIT) {
            int s2 = (it + 2) % NSTG;
            load_stage(s2, (it + 2) * BK);
        }
        asm volatile("cp.async.commit_group;\n");   // always: uniform group count
    }

    int g = lane >> 2, tg = lane & 3;
#pragma unroll
    for (int mi = 0; mi < 4; mi++)
#pragma unroll
        for (int ni = 0; ni < 4; ni++)
#pragma unroll
            for (int h = 0; h < 2; h++) {
                int m = wm + mi * 16 + g + h * 8;
                int n = n0 + wn + ni * 8 + 2 * tg;
                float v0 = acc[mi][ni][h * 2 + 0] + bias[e * ND + n];
                float v1 = acc[mi][ni][h * 2 + 1] + bias[e * ND + n + 1];
                if (FIRST) {
                    if (s_tok[m] < 0) continue;
                    size_t orow = (size_t)(row0 + m) * ND + n;
                    v0 = gelu_exact(v0);
                    v1 = gelu_exact(v1);
                    bf16 h0 = __float2bfloat16(v0), h1 = __float2bfloat16(v1);
                    bf16 l0 = __float2bfloat16(v0 - __bfloat162float(h0));
                    bf16 l1 = __float2bfloat16(v1 - __bfloat162float(h1));
                    bf162 ph; ph.x = h0; ph.y = h1;
                    bf162 pl; pl.x = l0; pl.y = l1;
                    *(bf162*)&g_hh[orow] = ph;
                    *(bf162*)&g_hl[orow] = pl;
                } else {
                    int tok = s_tok[m];
                    if (tok < 0) continue;
                    float w = s_w[m];
                    atomicAdd(&out[(size_t)tok * ND + n],     v0 * w);
                    atomicAdd(&out[(size_t)tok * ND + n + 1], v1 * w);
                }
            }
}

// ---------------- aux loss -------------------------------------------------
__global__ void aux_k(float* __restrict__ out, int out_size) {
    if (out_size <= T_TOK * D_IN) return;
    float s = 0.f;
    for (int e = 0; e < NE; e++) {
        float mean_prob = g_prob_sum[e] / (float)T_TOK;
        float frac = (float)g_count[e] / (float)(T_TOK * TOPK);
        s += mean_prob * frac;
    }
    out[T_TOK * D_IN] = (float)NE * s;
}

// ---------------- launch ---------------------------------------------------
extern "C" void kernel_launch(void* const* d_in, const int* in_sizes, int n_in,
                              void* d_out, int out_size) {
    const float* x   = (const float*)d_in[0];
    const float* gw  = (const float*)d_in[1];
    const float* W1  = (const float*)d_in[2];
    const float* b1  = (const float*)d_in[3];
    const float* W2  = (const float*)d_in[4];
    const float* b2  = (const float*)d_in[5];
    float* out = (float*)d_out;

    cudaFuncSetAttribute(gemm_mma<D_IN, D_HID, true>,
                         cudaFuncAttributeMaxDynamicSharedMemorySize, SMEM_BYTES);
    cudaFuncSetAttribute(gemm_mma<D_HID, D_IN, false>,
                         cudaFuncAttributeMaxDynamicSharedMemorySize, SMEM_BYTES);

    bf16 *xh, *xl, *w1h, *w1l, *w2h, *w2l, *hh, *hl;
    cudaGetSymbolAddress((void**)&xh,  g_xh);
    cudaGetSymbolAddress((void**)&xl,  g_xl);
    cudaGetSymbolAddress((void**)&w1h, g_w1h);
    cudaGetSymbolAddress((void**)&w1l, g_w1l);
    cudaGetSymbolAddress((void**)&w2h, g_w2h);
    cudaGetSymbolAddress((void**)&w2l, g_w2l);
    cudaGetSymbolAddress((void**)&hh,  g_hh);
    cudaGetSymbolAddress((void**)&hl,  g_hl);

    // launch 0: fused split of x/W1/W2 + init of counters/ptok
    split_all<<<NTOT4 / 256, 256>>>((const float4*)x, (const float4*)W1, (const float4*)W2);
    // launch 1: router + zero output
    prep_k<<<T_TOK * D_IN / 4 / 256, 256>>>(x, gw, (float4*)out);
    // launch 2: offsets + scatter (single block)
    route_k<<<1, 256>>>();

    // launch 3 (profiled slot): GEMM1
    gemm_mma<D_IN, D_HID, true>
        <<<dim3(D_HID / BN, MTILES), 256, SMEM_BYTES>>>(xh, xl, w1h, w1l, b1, out);
    // launch 4: GEMM2 + fused combine
    gemm_mma<D_HID, D_IN, false>
        <<<dim3(D_IN / BN, MTILES), 256, SMEM_BYTES>>>(hh, hl, w2h, w2l, b2, out);

    // launch 5: aux loss
    aux_k<<<1, 1>>>(out, out_size);
}

// round 16
// speedup vs baseline: 1.5091x; 1.3670x over previous
#include <cuda_runtime.h>
#include <cuda_fp16.h>
#include <math.h>
#include <stdint.h>

#define T_TOK  8192
#define D_IN   1024
#define D_HID  4096
#define NE     8
#define TOPK   2

#define BM 128
#define BN 128
#define BK 32
#define PADM   (T_TOK*TOPK + NE*BM)   /* 17408 */
#define MTILES (PADM/BM)              /* 136 */

#define APAD 40    /* halfs per A smem row (32 data + 8 pad) */
#define BPAD 136   /* halfs per B smem row (128 data + 8 pad) */
#define AH_OFF 0
#define AL_OFF (BM*APAD)                 /* 5120 halfs */
#define B_OFF  (2*BM*APAD)               /* 10240 halfs */
#define ST_H   (2*BM*APAD + BK*BPAD)     /* 14592 halfs per stage */
#define NSTG   3
#define SMEM_BYTES (NSTG*ST_H*2)         /* 87552 B -> 2 CTAs/SM */

typedef __half  h16;
typedef __half2 h162;

// ---------------- scratch (static device globals; no allocation) ----------
__device__ __align__(16) h16 g_xh [(size_t)T_TOK*D_IN];
__device__ __align__(16) h16 g_xl [(size_t)T_TOK*D_IN];
__device__ __align__(16) h16 g_w1h[(size_t)NE*D_IN*D_HID];
__device__ __align__(16) h16 g_w2h[(size_t)NE*D_HID*D_IN];
__device__ __align__(16) h16 g_hh [(size_t)PADM*D_HID];
__device__ __align__(16) h16 g_hl [(size_t)PADM*D_HID];
__device__ int   g_sel[T_TOK*TOPK];
__device__ float g_wt [T_TOK*TOPK];
__device__ float g_wtp[PADM];
__device__ float g_prob_sum[NE];
__device__ int   g_count[NE];
__device__ int   g_fill[NE];
__device__ int   g_poff[NE+1];
__device__ int   g_ptot;
__device__ int   g_ptok[PADM];

// ---------------- launch 0: split x (hi/lo) + convert W1/W2 + init --------
#define NX4  (T_TOK*D_IN/4)
#define NW4  (NE*D_IN*D_HID/4)
#define NTOT4 (NX4 + 2*NW4)

__global__ void split_all(const float4* __restrict__ x, const float4* __restrict__ W1,
                          const float4* __restrict__ W2) {
    int i = blockIdx.x * blockDim.x + threadIdx.x;
    if (i < PADM) g_ptok[i] = -1;
    if (i < NE) { g_prob_sum[i] = 0.f; g_count[i] = 0; g_fill[i] = 0; }

    if (i < NX4) {
        float4 v = x[i];
        h16 h0 = __float2half_rn(v.x), h1 = __float2half_rn(v.y);
        h16 h2 = __float2half_rn(v.z), h3 = __float2half_rn(v.w);
        h16 l0 = __float2half_rn(v.x - __half2float(h0));
        h16 l1 = __float2half_rn(v.y - __half2float(h1));
        h16 l2 = __float2half_rn(v.z - __half2float(h2));
        h16 l3 = __float2half_rn(v.w - __half2float(h3));
        ((h162*)g_xh)[2*i]   = h162(h0, h1);
        ((h162*)g_xh)[2*i+1] = h162(h2, h3);
        ((h162*)g_xl)[2*i]   = h162(l0, l1);
        ((h162*)g_xl)[2*i+1] = h162(l2, l3);
    } else if (i < NX4 + NW4) {
        int j = i - NX4;
        float4 v = W1[j];
        ((h162*)g_w1h)[2*j]   = __float22half2_rn(make_float2(v.x, v.y));
        ((h162*)g_w1h)[2*j+1] = __float22half2_rn(make_float2(v.z, v.w));
    } else if (i < NTOT4) {
        int j = i - NX4 - NW4;
        float4 v = W2[j];
        ((h162*)g_w2h)[2*j]   = __float22half2_rn(make_float2(v.x, v.y));
        ((h162*)g_w2h)[2*j+1] = __float22half2_rn(make_float2(v.z, v.w));
    }
}

// ---------------- launch 1: router (blocks 0..1023) + zero out (all) -------
__global__ void prep_k(const float* __restrict__ x, const float* __restrict__ gw,
                       float4* __restrict__ out4) {
    {
        int i = blockIdx.x * blockDim.x + threadIdx.x;
        if (i < T_TOK * D_IN / 4) out4[i] = make_float4(0.f, 0.f, 0.f, 0.f);
    }
    if (blockIdx.x >= T_TOK / 8) return;

    __shared__ float sg[D_IN * NE];
    __shared__ float s_prob[NE];
    __shared__ int   s_cnt[NE];
    int tid = threadIdx.x;
    for (int i = tid; i < D_IN * NE; i += 256) sg[i] = gw[i];
    if (tid < NE) { s_prob[tid] = 0.f; s_cnt[tid] = 0; }
    __syncthreads();

    int warp = tid >> 5, lane = tid & 31;
    int t = blockIdx.x * 8 + warp;
    const float* xr = x + (size_t)t * D_IN;

    float acc[NE];
#pragma unroll
    for (int e = 0; e < NE; e++) acc[e] = 0.f;
    for (int i = lane; i < D_IN; i += 32) {
        float xv = xr[i];
        const float* g = &sg[i * NE];
#pragma unroll
        for (int e = 0; e < NE; e++) acc[e] += xv * g[e];
    }
#pragma unroll
    for (int e = 0; e < NE; e++)
        for (int o = 16; o; o >>= 1) acc[e] += __shfl_xor_sync(0xffffffffu, acc[e], o);

    if (lane == 0) {
        float mx = acc[0];
#pragma unroll
        for (int e = 1; e < NE; e++) mx = fmaxf(mx, acc[e]);
        float p[NE], s = 0.f;
#pragma unroll
        for (int e = 0; e < NE; e++) { p[e] = expf(acc[e] - mx); s += p[e]; }
        float inv = 1.f / s;
#pragma unroll
        for (int e = 0; e < NE; e++) p[e] *= inv;

        int i1 = 0;
#pragma unroll
        for (int e = 1; e < NE; e++) if (p[e] > p[i1]) i1 = e;
        int i2 = (i1 == 0) ? 1 : 0;
#pragma unroll
        for (int e = 0; e < NE; e++) if (e != i1 && p[e] > p[i2]) i2 = e;

        float d = p[i1] + p[i2] + 1e-6f;
        g_sel[t*2]   = i1;  g_sel[t*2+1] = i2;
        g_wt [t*2]   = p[i1] / d;
        g_wt [t*2+1] = p[i2] / d;
#pragma unroll
        for (int e = 0; e < NE; e++) atomicAdd(&s_prob[e], p[e]);
        atomicAdd(&s_cnt[i1], 1);
        atomicAdd(&s_cnt[i2], 1);
    }
    __syncthreads();
    if (tid < NE) {
        atomicAdd(&g_prob_sum[tid], s_prob[tid]);
        atomicAdd(&g_count[tid], s_cnt[tid]);
    }
}

// ---------------- launch 2: offsets + scatter (single block) ---------------
__global__ void route_k() {
    int tid = threadIdx.x;
    if (tid == 0) {
        int off = 0;
        for (int e = 0; e < NE; e++) {
            g_poff[e] = off;
            off += ((g_count[e] + BM - 1) / BM) * BM;
        }
        g_poff[NE] = off;
        g_ptot = off;
    }
    __syncthreads();
    for (int t = tid; t < T_TOK; t += 256) {
#pragma unroll
        for (int k = 0; k < TOPK; k++) {
            int e = g_sel[t*2 + k];
            int j = atomicAdd(&g_fill[e], 1);
            int pos = g_poff[e] + j;
            g_ptok[pos] = t;
            g_wtp[pos]  = g_wt[t*2 + k];
        }
    }
}

// ---------------- MMA helpers ----------------------------------------------
__device__ __forceinline__ void cpa16(uint32_t dst, const void* src) {
    asm volatile("cp.async.cg.shared.global [%0], [%1], 16;\n" :: "r"(dst), "l"(src));
}
__device__ __forceinline__ void ldmx4(uint32_t* r, uint32_t addr) {
    asm volatile("ldmatrix.sync.aligned.m8n8.x4.shared.b16 {%0,%1,%2,%3}, [%4];\n"
        : "=r"(r[0]), "=r"(r[1]), "=r"(r[2]), "=r"(r[3]) : "r"(addr));
}
__device__ __forceinline__ void ldmx4t(uint32_t* r, uint32_t addr) {
    asm volatile("ldmatrix.sync.aligned.m8n8.x4.trans.shared.b16 {%0,%1,%2,%3}, [%4];\n"
        : "=r"(r[0]), "=r"(r[1]), "=r"(r[2]), "=r"(r[3]) : "r"(addr));
}
__device__ __forceinline__ void mma16816(float* c, const uint32_t* a, const uint32_t* b) {
    asm volatile("mma.sync.aligned.m16n8k16.row.col.f32.f16.f16.f32 "
        "{%0,%1,%2,%3}, {%4,%5,%6,%7}, {%8,%9}, {%0,%1,%2,%3};\n"
        : "+f"(c[0]), "+f"(c[1]), "+f"(c[2]), "+f"(c[3])
        : "r"(a[0]), "r"(a[1]), "r"(a[2]), "r"(a[3]), "r"(b[0]), "r"(b[1]));
}
__device__ __forceinline__ float gelu_exact(float v) {
    return 0.5f * v * (1.0f + erff(v * 0.70710678118654752440f));
}

// ---------------- fp16 (2,1)-split MMA GEMM (128x128, 2 CTAs/SM) -----------
// C = (Ah + Al) @ B   with A fp16 hi/lo, B single fp16, fp32 accumulate.
// FIRST=true : A gathered by token, epilogue = bias+GELU -> hi/lo fp16 hidden
// FIRST=false: A = permuted hidden rows, epilogue = (acc+bias)*w atomicAdd out
template<int KD, int ND, bool FIRST>
__global__ void __launch_bounds__(256, 2) gemm_mma(
    const h16* __restrict__ Ah_g, const h16* __restrict__ Al_g,
    const h16* __restrict__ B_g,
    const float* __restrict__ bias, float* __restrict__ out)
{
    extern __shared__ h16 smem[];
    __shared__ int   s_tok[BM];
    __shared__ float s_w[BM];

    int row0 = blockIdx.y * BM;
    if (row0 >= g_ptot) return;
    int e = 0;
    while (row0 >= g_poff[e + 1]) e++;
    int n0 = blockIdx.x * BN;

    int tid = threadIdx.x;
    if (tid < BM) {
        int t = g_ptok[row0 + tid];
        s_tok[tid] = t;
        if (!FIRST) s_w[tid] = g_wtp[row0 + tid];
    }
    __syncthreads();

    const h16* B_e = B_g + (size_t)e * KD * ND + n0;

    uint32_t smem_base = (uint32_t)__cvta_generic_to_shared(smem);

    auto load_stage = [&](int stage, int k0) {
        uint32_t sb = smem_base + (uint32_t)stage * (ST_H * 2);
        // A: 128 rows x 4 chunks(16B) x {h,l} = 1024 cp.async (512 c-values)
#pragma unroll
        for (int m = 0; m < 2; m++) {
            int c = tid + m * 256;              // 0..511
            int r = c >> 2, j = c & 3;
            int tk = s_tok[r];
            size_t arow = FIRST ? (size_t)(tk < 0 ? 0 : tk) * KD : (size_t)(row0 + r) * KD;
            uint32_t offA = (uint32_t)(r * APAD + j * 8) * 2;
            cpa16(sb + AH_OFF * 2 + offA, Ah_g + arow + k0 + j * 8);
            cpa16(sb + AL_OFF * 2 + offA, Al_g + arow + k0 + j * 8);
        }
        // B: 32 rows x 16 chunks(16B) = 512 cp.async
#pragma unroll
        for (int m = 0; m < 2; m++) {
            int c = tid + m * 256;
            int rb = c >> 4, jb = c & 15;
            size_t brow = (size_t)(k0 + rb) * ND + jb * 8;
            uint32_t offB = (uint32_t)(rb * BPAD + jb * 8) * 2;
            if (m == 0)  // only 512 total: first 256-thread pass covers rows 0..15
                cpa16(sb + B_OFF * 2 + offB, B_e + brow);
            else
                cpa16(sb + B_OFF * 2 + offB, B_e + brow);
        }
    };

    int lane = tid & 31, warp = tid >> 5;
    int wm = (warp >> 2) * 64;
    int wn = (warp & 3) * 32;
    uint32_t rowSel = (lane & 7) + ((lane >> 3) & 1) * 8;
    uint32_t colSel = (lane >> 4) * 8;

    float acc[4][4][4];
#pragma unroll
    for (int i = 0; i < 4; i++)
#pragma unroll
        for (int j = 0; j < 4; j++)
#pragma unroll
            for (int q = 0; q < 4; q++) acc[i][j][q] = 0.f;

    auto compute = [&](int stage) {
        uint32_t sb = smem_base + (uint32_t)stage * (ST_H * 2);
        uint32_t ah = sb + AH_OFF * 2, al = sb + AL_OFF * 2;
        uint32_t bb = sb + B_OFF * 2;
#pragma unroll
        for (int kk = 0; kk < 2; kk++) {
            int k16 = kk * 16;
            uint32_t bF[2][4];
#pragma unroll
            for (int nj = 0; nj < 2; nj++) {
                uint32_t off = (uint32_t)((k16 + rowSel) * BPAD + wn + nj * 16 + colSel) * 2;
                ldmx4t(bF[nj], bb + off);
            }
            uint32_t aF[4][4];
#pragma unroll
            for (int mi = 0; mi < 4; mi++) {
                uint32_t off = (uint32_t)((wm + mi * 16 + rowSel) * APAD + k16 + colSel) * 2;
                ldmx4(aF[mi], ah + off);
            }
#pragma unroll
            for (int mi = 0; mi < 4; mi++)
#pragma unroll
                for (int ni = 0; ni < 4; ni++)
                    mma16816(acc[mi][ni], aF[mi], &bF[ni >> 1][(ni & 1) * 2]);
#pragma unroll
            for (int mi = 0; mi < 4; mi++) {
                uint32_t off = (uint32_t)((wm + mi * 16 + rowSel) * APAD + k16 + colSel) * 2;
                ldmx4(aF[mi], al + off);
            }
#pragma unroll
            for (int mi = 0; mi < 4; mi++)
#pragma unroll
                for (int ni = 0; ni < 4; ni++)
                    mma16816(acc[mi][ni], aF[mi], &bF[ni >> 1][(ni & 1) * 2]);
        }
    };

    const int NIT = KD / BK;
    load_stage(0, 0);
    asm volatile("cp.async.commit_group;\n");
    load_stage(1, BK);
    asm volatile("cp.async.commit_group;\n");

#pragma unroll 1
    for (int it = 0; it < NIT; ++it) {
        asm volatile("cp.async.wait_group 1;\n");
        __syncthreads();
        int s = it % NSTG;
        compute(s);
        if (it + 2 < NIT) {
            int s2 = (it + 2) % NSTG;
            load_stage(s2, (it + 2) * BK);
        }
        asm volatile("cp.async.commit_group;\n");   // always: uniform group count
    }

    int g = lane >> 2, tg = lane & 3;
#pragma unroll
    for (int mi = 0; mi < 4; mi++)
#pragma unroll
        for (int ni = 0; ni < 4; ni++)
#pragma unroll
            for (int h = 0; h < 2; h++) {
                int m = wm + mi * 16 + g + h * 8;
                int n = n0 + wn + ni * 8 + 2 * tg;
                float v0 = acc[mi][ni][h * 2 + 0] + bias[e * ND + n];
                float v1 = acc[mi][ni][h * 2 + 1] + bias[e * ND + n + 1];
                if (FIRST) {
                    if (s_tok[m] < 0) continue;
                    size_t orow = (size_t)(row0 + m) * ND + n;
                    v0 = gelu_exact(v0);
                    v1 = gelu_exact(v1);
                    h16 h0 = __float2half_rn(v0), h1 = __float2half_rn(v1);
                    h16 l0 = __float2half_rn(v0 - __half2float(h0));
                    h16 l1 = __float2half_rn(v1 - __half2float(h1));
                    *(h162*)&g_hh[orow] = h162(h0, h1);
                    *(h162*)&g_hl[orow] = h162(l0, l1);
                } else {
                    int tok = s_tok[m];
                    if (tok < 0) continue;
                    float w = s_w[m];
                    atomicAdd(&out[(size_t)tok * ND + n],     v0 * w);
                    atomicAdd(&out[(size_t)tok * ND + n + 1], v1 * w);
                }
            }
}

// ---------------- aux loss -------------------------------------------------
__global__ void aux_k(float* __restrict__ out, int out_size) {
    if (out_size <= T_TOK * D_IN) return;
    float s = 0.f;
    for (int e = 0; e < NE; e++) {
        float mean_prob = g_prob_sum[e] / (float)T_TOK;
        float frac = (float)g_count[e] / (float)(T_TOK * TOPK);
        s += mean_prob * frac;
    }
    out[T_TOK * D_IN] = (float)NE * s;
}

// ---------------- launch ---------------------------------------------------
extern "C" void kernel_launch(void* const* d_in, const int* in_sizes, int n_in,
                              void* d_out, int out_size) {
    const float* x   = (const float*)d_in[0];
    const float* gw  = (const float*)d_in[1];
    const float* W1  = (const float*)d_in[2];
    const float* b1  = (const float*)d_in[3];
    const float* W2  = (const float*)d_in[4];
    const float* b2  = (const float*)d_in[5];
    float* out = (float*)d_out;

    cudaFuncSetAttribute(gemm_mma<D_IN, D_HID, true>,
                         cudaFuncAttributeMaxDynamicSharedMemorySize, SMEM_BYTES);
    cudaFuncSetAttribute(gemm_mma<D_HID, D_IN, false>,
                         cudaFuncAttributeMaxDynamicSharedMemorySize, SMEM_BYTES);

    h16 *xh, *xl, *w1h, *w2h, *hh, *hl;
    cudaGetSymbolAddress((void**)&xh,  g_xh);
    cudaGetSymbolAddress((void**)&xl,  g_xl);
    cudaGetSymbolAddress((void**)&w1h, g_w1h);
    cudaGetSymbolAddress((void**)&w2h, g_w2h);
    cudaGetSymbolAddress((void**)&hh,  g_hh);
    cudaGetSymbolAddress((void**)&hl,  g_hl);

    // launch 0: split x (hi/lo) + convert W1/W2 + init counters/ptok
    split_all<<<NTOT4 / 256, 256>>>((const float4*)x, (const float4*)W1, (const float4*)W2);
    // launch 1: router + zero output
    prep_k<<<T_TOK * D_IN / 4 / 256, 256>>>(x, gw, (float4*)out);
    // launch 2: offsets + scatter (single block)
    route_k<<<1, 256>>>();

    // launch 3 (profiled slot): GEMM1
    gemm_mma<D_IN, D_HID, true>
        <<<dim3(D_HID / BN, MTILES), 256, SMEM_BYTES>>>(xh, xl, w1h, b1, out);
    // launch 4: GEMM2 + fused combine
    gemm_mma<D_HID, D_IN, false>
        <<<dim3(D_IN / BN, MTILES), 256, SMEM_BYTES>>>(hh, hl, w2h, b2, out);

    // launch 5: aux loss
    aux_k<<<1, 1>>>(out, out_size);
}

// round 17
// speedup vs baseline: 2.4618x; 1.6313x over previous
#include <cuda_runtime.h>
#include <cuda_fp16.h>
#include <math.h>
#include <stdint.h>

#define T_TOK  8192
#define D_IN   1024
#define D_HID  4096
#define NE     8
#define TOPK   2

#define BM 128
#define BN 128
#define BK 32
#define PADM   (T_TOK*TOPK + NE*BM)   /* 17408 */
#define MTILES (PADM/BM)              /* 136 */

#define APAD 40    /* halfs per A smem row (32 data + 8 pad) */
#define BPAD 136   /* halfs per B smem row (128 data + 8 pad) */
#define A_OFF  0
#define B_OFF  (BM*APAD)                 /* 5120 halfs */
#define ST_H   (BM*APAD + BK*BPAD)       /* 9472 halfs per stage = 18944 B */
#define NSTG   4
#define SMEM_BYTES (NSTG*ST_H*2)         /* 75776 B -> 2 CTAs/SM */

typedef __half  h16;
typedef __half2 h162;

// ---------------- scratch (static device globals; no allocation) ----------
__device__ __align__(16) h16 g_xh [(size_t)T_TOK*D_IN];
__device__ __align__(16) h16 g_w1h[(size_t)NE*D_IN*D_HID];
__device__ __align__(16) h16 g_w2h[(size_t)NE*D_HID*D_IN];
__device__ __align__(16) h16 g_hh [(size_t)PADM*D_HID];
__device__ int   g_sel[T_TOK*TOPK];
__device__ float g_wt [T_TOK*TOPK];
__device__ float g_wtp[PADM];
__device__ float g_prob_sum[NE];
__device__ int   g_count[NE];
__device__ int   g_fill[NE];
__device__ int   g_poff[NE+1];
__device__ int   g_ptot;
__device__ int   g_ptok[PADM];

// ---------------- launch 0: convert x/W1/W2 to fp16 + init -----------------
#define NX4  (T_TOK*D_IN/4)
#define NW4  (NE*D_IN*D_HID/4)
#define NTOT4 (NX4 + 2*NW4)

__global__ void split_all(const float4* __restrict__ x, const float4* __restrict__ W1,
                          const float4* __restrict__ W2) {
    int i = blockIdx.x * blockDim.x + threadIdx.x;
    if (i < PADM) g_ptok[i] = -1;
    if (i < NE) { g_prob_sum[i] = 0.f; g_count[i] = 0; g_fill[i] = 0; }

    if (i < NX4) {
        float4 v = x[i];
        ((h162*)g_xh)[2*i]   = __float22half2_rn(make_float2(v.x, v.y));
        ((h162*)g_xh)[2*i+1] = __float22half2_rn(make_float2(v.z, v.w));
    } else if (i < NX4 + NW4) {
        int j = i - NX4;
        float4 v = W1[j];
        ((h162*)g_w1h)[2*j]   = __float22half2_rn(make_float2(v.x, v.y));
        ((h162*)g_w1h)[2*j+1] = __float22half2_rn(make_float2(v.z, v.w));
    } else if (i < NTOT4) {
        int j = i - NX4 - NW4;
        float4 v = W2[j];
        ((h162*)g_w2h)[2*j]   = __float22half2_rn(make_float2(v.x, v.y));
        ((h162*)g_w2h)[2*j+1] = __float22half2_rn(make_float2(v.z, v.w));
    }
}

// ---------------- launch 1: router (blocks 0..1023) + zero out (all) -------
__global__ void prep_k(const float* __restrict__ x, const float* __restrict__ gw,
                       float4* __restrict__ out4) {
    {
        int i = blockIdx.x * blockDim.x + threadIdx.x;
        if (i < T_TOK * D_IN / 4) out4[i] = make_float4(0.f, 0.f, 0.f, 0.f);
    }
    if (blockIdx.x >= T_TOK / 8) return;

    __shared__ float sg[D_IN * NE];
    __shared__ float s_prob[NE];
    __shared__ int   s_cnt[NE];
    int tid = threadIdx.x;
    for (int i = tid; i < D_IN * NE; i += 256) sg[i] = gw[i];
    if (tid < NE) { s_prob[tid] = 0.f; s_cnt[tid] = 0; }
    __syncthreads();

    int warp = tid >> 5, lane = tid & 31;
    int t = blockIdx.x * 8 + warp;
    const float* xr = x + (size_t)t * D_IN;

    float acc[NE];
#pragma unroll
    for (int e = 0; e < NE; e++) acc[e] = 0.f;
    for (int i = lane; i < D_IN; i += 32) {
        float xv = xr[i];
        const float* g = &sg[i * NE];
#pragma unroll
        for (int e = 0; e < NE; e++) acc[e] += xv * g[e];
    }
#pragma unroll
    for (int e = 0; e < NE; e++)
        for (int o = 16; o; o >>= 1) acc[e] += __shfl_xor_sync(0xffffffffu, acc[e], o);

    if (lane == 0) {
        float mx = acc[0];
#pragma unroll
        for (int e = 1; e < NE; e++) mx = fmaxf(mx, acc[e]);
        float p[NE], s = 0.f;
#pragma unroll
        for (int e = 0; e < NE; e++) { p[e] = expf(acc[e] - mx); s += p[e]; }
        float inv = 1.f / s;
#pragma unroll
        for (int e = 0; e < NE; e++) p[e] *= inv;

        int i1 = 0;
#pragma unroll
        for (int e = 1; e < NE; e++) if (p[e] > p[i1]) i1 = e;
        int i2 = (i1 == 0) ? 1 : 0;
#pragma unroll
        for (int e = 0; e < NE; e++) if (e != i1 && p[e] > p[i2]) i2 = e;

        float d = p[i1] + p[i2] + 1e-6f;
        g_sel[t*2]   = i1;  g_sel[t*2+1] = i2;
        g_wt [t*2]   = p[i1] / d;
        g_wt [t*2+1] = p[i2] / d;
#pragma unroll
        for (int e = 0; e < NE; e++) atomicAdd(&s_prob[e], p[e]);
        atomicAdd(&s_cnt[i1], 1);
        atomicAdd(&s_cnt[i2], 1);
    }
    __syncthreads();
    if (tid < NE) {
        atomicAdd(&g_prob_sum[tid], s_prob[tid]);
        atomicAdd(&g_count[tid], s_cnt[tid]);
    }
}

// ---------------- launch 2: offsets + scatter (single block) ---------------
__global__ void route_k() {
    int tid = threadIdx.x;
    if (tid == 0) {
        int off = 0;
        for (int e = 0; e < NE; e++) {
            g_poff[e] = off;
            off += ((g_count[e] + BM - 1) / BM) * BM;
        }
        g_poff[NE] = off;
        g_ptot = off;
    }
    __syncthreads();
    for (int t = tid; t < T_TOK; t += 256) {
#pragma unroll
        for (int k = 0; k < TOPK; k++) {
            int e = g_sel[t*2 + k];
            int j = atomicAdd(&g_fill[e], 1);
            int pos = g_poff[e] + j;
            g_ptok[pos] = t;
            g_wtp[pos]  = g_wt[t*2 + k];
        }
    }
}

// ---------------- MMA helpers ----------------------------------------------
__device__ __forceinline__ void cpa16(uint32_t dst, const void* src) {
    asm volatile("cp.async.cg.shared.global [%0], [%1], 16;\n" :: "r"(dst), "l"(src));
}
__device__ __forceinline__ void ldmx4(uint32_t* r, uint32_t addr) {
    asm volatile("ldmatrix.sync.aligned.m8n8.x4.shared.b16 {%0,%1,%2,%3}, [%4];\n"
        : "=r"(r[0]), "=r"(r[1]), "=r"(r[2]), "=r"(r[3]) : "r"(addr));
}
__device__ __forceinline__ void ldmx4t(uint32_t* r, uint32_t addr) {
    asm volatile("ldmatrix.sync.aligned.m8n8.x4.trans.shared.b16 {%0,%1,%2,%3}, [%4];\n"
        : "=r"(r[0]), "=r"(r[1]), "=r"(r[2]), "=r"(r[3]) : "r"(addr));
}
__device__ __forceinline__ void mma16816(float* c, const uint32_t* a, const uint32_t* b) {
    asm volatile("mma.sync.aligned.m16n8k16.row.col.f32.f16.f16.f32 "
        "{%0,%1,%2,%3}, {%4,%5,%6,%7}, {%8,%9}, {%0,%1,%2,%3};\n"
        : "+f"(c[0]), "+f"(c[1]), "+f"(c[2]), "+f"(c[3])
        : "r"(a[0]), "r"(a[1]), "r"(a[2]), "r"(a[3]), "r"(b[0]), "r"(b[1]));
}
__device__ __forceinline__ float gelu_exact(float v) {
    return 0.5f * v * (1.0f + erff(v * 0.70710678118654752440f));
}

// ---------------- single-pass fp16 MMA GEMM (128x128, 2 CTAs/SM) -----------
// FIRST=true : A gathered by token, epilogue = bias+GELU -> fp16 hidden
// FIRST=false: A = permuted hidden rows, epilogue = (acc+bias)*w atomicAdd out
template<int KD, int ND, bool FIRST>
__global__ void __launch_bounds__(256, 2) gemm_mma(
    const h16* __restrict__ A_g, const h16* __restrict__ B_g,
    const float* __restrict__ bias, float* __restrict__ out)
{
    extern __shared__ h16 smem[];
    __shared__ int   s_tok[BM];
    __shared__ float s_w[BM];

    int row0 = blockIdx.y * BM;
    if (row0 >= g_ptot) return;
    int e = 0;
    while (row0 >= g_poff[e + 1]) e++;
    int n0 = blockIdx.x * BN;

    int tid = threadIdx.x;
    if (tid < BM) {
        int t = g_ptok[row0 + tid];
        s_tok[tid] = t;
        if (!FIRST) s_w[tid] = g_wtp[row0 + tid];
    }
    __syncthreads();

    const h16* B_e = B_g + (size_t)e * KD * ND + n0;

    uint32_t smem_base = (uint32_t)__cvta_generic_to_shared(smem);

    auto load_stage = [&](int stage, int k0) {
        uint32_t sb = smem_base + (uint32_t)stage * (ST_H * 2);
        // A: 128 rows x 4 chunks(16B) = 512 cp.async
#pragma unroll
        for (int m = 0; m < 2; m++) {
            int c = tid + m * 256;              // 0..511
            int r = c >> 2, j = c & 3;
            int tk = s_tok[r];
            size_t arow = FIRST ? (size_t)(tk < 0 ? 0 : tk) * KD : (size_t)(row0 + r) * KD;
            uint32_t offA = (uint32_t)(r * APAD + j * 8) * 2;
            cpa16(sb + A_OFF * 2 + offA, A_g + arow + k0 + j * 8);
        }
        // B: 32 rows x 16 chunks(16B) = 512 cp.async
#pragma unroll
        for (int m = 0; m < 2; m++) {
            int c = tid + m * 256;
            int rb = c >> 4, jb = c & 15;
            size_t brow = (size_t)(k0 + rb) * ND + jb * 8;
            uint32_t offB = (uint32_t)(rb * BPAD + jb * 8) * 2;
            cpa16(sb + B_OFF * 2 + offB, B_e + brow);
        }
    };

    int lane = tid & 31, warp = tid >> 5;
    int wm = (warp >> 2) * 64;
    int wn = (warp & 3) * 32;
    uint32_t rowSel = (lane & 7) + ((lane >> 3) & 1) * 8;
    uint32_t colSel = (lane >> 4) * 8;

    float acc[4][4][4];
#pragma unroll
    for (int i = 0; i < 4; i++)
#pragma unroll
        for (int j = 0; j < 4; j++)
#pragma unroll
            for (int q = 0; q < 4; q++) acc[i][j][q] = 0.f;

    auto compute = [&](int stage) {
        uint32_t sb = smem_base + (uint32_t)stage * (ST_H * 2);
        uint32_t aa = sb + A_OFF * 2;
        uint32_t bb = sb + B_OFF * 2;
#pragma unroll
        for (int kk = 0; kk < 2; kk++) {
            int k16 = kk * 16;
            uint32_t bF[2][4];
#pragma unroll
            for (int nj = 0; nj < 2; nj++) {
                uint32_t off = (uint32_t)((k16 + rowSel) * BPAD + wn + nj * 16 + colSel) * 2;
                ldmx4t(bF[nj], bb + off);
            }
            uint32_t aF[4][4];
#pragma unroll
            for (int mi = 0; mi < 4; mi++) {
                uint32_t off = (uint32_t)((wm + mi * 16 + rowSel) * APAD + k16 + colSel) * 2;
                ldmx4(aF[mi], aa + off);
            }
#pragma unroll
            for (int mi = 0; mi < 4; mi++)
#pragma unroll
                for (int ni = 0; ni < 4; ni++)
                    mma16816(acc[mi][ni], aF[mi], &bF[ni >> 1][(ni & 1) * 2]);
        }
    };

    const int NIT = KD / BK;
    // prologue: fill 3 of 4 stages
    load_stage(0, 0);
    asm volatile("cp.async.commit_group;\n");
    load_stage(1, BK);
    asm volatile("cp.async.commit_group;\n");
    load_stage(2, 2 * BK);
    asm volatile("cp.async.commit_group;\n");

#pragma unroll 1
    for (int it = 0; it < NIT; ++it) {
        asm volatile("cp.async.wait_group 2;\n");
        __syncthreads();
        compute(it & (NSTG - 1));
        if (it + 3 < NIT) load_stage((it + 3) & (NSTG - 1), (it + 3) * BK);
        asm volatile("cp.async.commit_group;\n");   // always: uniform group count
    }

    int g = lane >> 2, tg = lane & 3;
#pragma unroll
    for (int mi = 0; mi < 4; mi++)
#pragma unroll
        for (int ni = 0; ni < 4; ni++)
#pragma unroll
            for (int h = 0; h < 2; h++) {
                int m = wm + mi * 16 + g + h * 8;
                int n = n0 + wn + ni * 8 + 2 * tg;
                float v0 = acc[mi][ni][h * 2 + 0] + bias[e * ND + n];
                float v1 = acc[mi][ni][h * 2 + 1] + bias[e * ND + n + 1];
                if (FIRST) {
                    if (s_tok[m] < 0) continue;
                    size_t orow = (size_t)(row0 + m) * ND + n;
                    v0 = gelu_exact(v0);
                    v1 = gelu_exact(v1);
                    *(h162*)&g_hh[orow] = __float22half2_rn(make_float2(v0, v1));
                } else {
                    int tok = s_tok[m];
                    if (tok < 0) continue;
                    float w = s_w[m];
                    atomicAdd(&out[(size_t)tok * ND + n],     v0 * w);
                    atomicAdd(&out[(size_t)tok * ND + n + 1], v1 * w);
                }
            }
}

// ---------------- aux loss -------------------------------------------------
__global__ void aux_k(float* __restrict__ out, int out_size) {
    if (out_size <= T_TOK * D_IN) return;
    float s = 0.f;
    for (int e = 0; e < NE; e++) {
        float mean_prob = g_prob_sum[e] / (float)T_TOK;
        float frac = (float)g_count[e] / (float)(T_TOK * TOPK);
        s += mean_prob * frac;
    }
    out[T_TOK * D_IN] = (float)NE * s;
}

// ---------------- launch ---------------------------------------------------
extern "C" void kernel_launch(void* const* d_in, const int* in_sizes, int n_in,
                              void* d_out, int out_size) {
    const float* x   = (const float*)d_in[0];
    const float* gw  = (const float*)d_in[1];
    const float* W1  = (const float*)d_in[2];
    const float* b1  = (const float*)d_in[3];
    const float* W2  = (const float*)d_in[4];
    const float* b2  = (const float*)d_in[5];
    float* out = (float*)d_out;

    cudaFuncSetAttribute(gemm_mma<D_IN, D_HID, true>,
                         cudaFuncAttributeMaxDynamicSharedMemorySize, SMEM_BYTES);
    cudaFuncSetAttribute(gemm_mma<D_HID, D_IN, false>,
                         cudaFuncAttributeMaxDynamicSharedMemorySize, SMEM_BYTES);

    h16 *xh, *w1h, *w2h, *hh;
    cudaGetSymbolAddress((void**)&xh,  g_xh);
    cudaGetSymbolAddress((void**)&w1h, g_w1h);
    cudaGetSymbolAddress((void**)&w2h, g_w2h);
    cudaGetSymbolAddress((void**)&hh,  g_hh);

    // launch 0: convert x/W1/W2 to fp16 + init counters/ptok
    split_all<<<NTOT4 / 256, 256>>>((const float4*)x, (const float4*)W1, (const float4*)W2);
    // launch 1: router + zero output
    prep_k<<<T_TOK * D_IN / 4 / 256, 256>>>(x, gw, (float4*)out);
    // launch 2: offsets + scatter (single block)
    route_k<<<1, 256>>>();

    // launch 3 (profiled slot): GEMM1
    gemm_mma<D_IN, D_HID, true>
        <<<dim3(D_HID / BN, MTILES), 256, SMEM_BYTES>>>(xh, w1h, b1, out);
    // launch 4: GEMM2 + fused combine
    gemm_mma<D_HID, D_IN, false>
        <<<dim3(D_IN / BN, MTILES), 256, SMEM_BYTES>>>(hh, w2h, b2, out);

    // launch 5: aux loss
    aux_k<<<1, 1>>>(out, out_size);
}